// round 16
// baseline (speedup 1.0000x reference)
#include <cuda_runtime.h>
#include <cuda_fp16.h>
#include <cstdint>

// Radon transform: out[b, n, t] = sum_h bilinear(img_b, R(theta_n) * grid(t, h))
// B=2, N=180 (angles = 0..179 deg), H=W=512.
//
// BATCH + ANGLE fusion (R13/R15) + NEW adaptive warp shape:
//   shape A (8t x 4p, h step 4)  for mid angles      rows ~ 8m+3M
//   shape B (16t x 2p, h step 2) for near-axis (4m<M) rows ~ 16m+M  (fewer lines)
// Shape B splits the h-range across warp pairs and combines via smem atomicAdd.
// One merged quad buffer: family stride QELEMS so the img2 load is an immediate
// offset off the same base. fp16 delta-quads, magic floor/fract, clamp-free
// interior, per-(angle,t-tile) h-interval zero skip.

#define IMG 512
#define NANG 180
#define QPITCH 516                    // quad row pitch; valid rows/cols 0..515
#define QELEMS (QPITCH * QPITCH)
#define MAGIC1 12582913.0f            // 2^23 + 2^22 + 1
#define MAGIC_BITS 0x4B400000u        // float bits of 12582912.0f
#define QROWB (QPITCH * 16u)          // bytes per quad row
#define FAM_BYTES (QELEMS * 16u)      // one family stride in bytes

// families: 0 = img normal, 1 = img2 normal, 2 = img transposed, 3 = img2 transposed
__device__ uint4 d_quads[4 * QELEMS];

__device__ __forceinline__ float pix(const float* img, int r, int c) {
    return ((unsigned)r < IMG && (unsigned)c < IMG) ? img[r * IMG + c] : 0.0f;
}
__device__ __forceinline__ unsigned packh2(float a, float b) {
    __half2 h = __floats2half2_rn(a, b);
    return *(const unsigned int*)&h;
}

__global__ void quad_kernel(const float* __restrict__ x) {
    int idx = blockIdx.x * blockDim.x + threadIdx.x;
    if (idx >= QELEMS) return;
    int r  = idx / QPITCH;
    int cc = idx - r * QPITCH;

    const float* img0 = x;
    const float* img1 = x + IMG * IMG;

    float a00 = pix(img0, r - 1, cc - 1), a10 = pix(img0, r - 1, cc);
    float a01 = pix(img0, r,     cc - 1), a11 = pix(img0, r,     cc);
    float b00 = pix(img1, r - 1, cc - 1), b10 = pix(img1, r - 1, cc);
    float b01 = pix(img1, r,     cc - 1), b11 = pix(img1, r,     cc);

    {   // img normal at (r, cc)
        uint4 q;
        q.x = packh2(a00, a01); q.y = packh2(a10 - a00, a11 - a01);
        q.z = packh2(b00, b01); q.w = packh2(b10 - b00, b11 - b01);
        d_quads[0 * QELEMS + idx] = q;
    }
    {   // img transposed at (cc, r)
        uint4 q;
        q.x = packh2(a00, a10); q.y = packh2(a01 - a00, a11 - a10);
        q.z = packh2(b00, b10); q.w = packh2(b01 - b00, b11 - b10);
        d_quads[2 * QELEMS + cc * QPITCH + r] = q;
    }
    int rq = 512 - cc;   // img2(r,c) = img(c, 511-r)
    if (rq >= 0) {
        {   // img2 normal at (rq, r)
            uint4 q;
            q.x = packh2(a10, a00); q.y = packh2(a11 - a10, a01 - a00);
            q.z = packh2(b10, b00); q.w = packh2(b11 - b10, b01 - b00);
            d_quads[1 * QELEMS + rq * QPITCH + r] = q;
        }
        {   // img2 transposed at (r, rq)
            uint4 q;
            q.x = packh2(a10, a11); q.y = packh2(a00 - a10, a01 - a11);
            q.z = packh2(b10, b11); q.w = packh2(b00 - b10, b01 - b11);
            d_quads[3 * QELEMS + r * QPITCH + rq] = q;
        }
    }
    if (cc < 3) {        // img2 rows/cols 513..515 are all-zero cells
        int e = 513 + cc;
        uint4 z = make_uint4(0u, 0u, 0u, 0u);
        d_quads[1 * QELEMS + e * QPITCH + r] = z;
        d_quads[3 * QELEMS + r * QPITCH + e] = z;
    }
}

// X = fast coord, Y = row coord; both in [-1, 512]. One call -> 4 outputs.
// qB (img2 family) = qA + FAM_BYTES (immediate offset off the same base).
__device__ __forceinline__ void sample_accum4(const uint4* __restrict__ qA,
                                              float X, float Y,
                                              float& a0, float& a1,
                                              float& a2, float& a3) {
    const float fxm = __fadd_rd(X, MAGIC1);
    const float fym = __fadd_rd(Y, MAGIC1);
    const float fx = X - (fxm - MAGIC1);
    const float fy = Y - (fym - MAGIC1);

    const unsigned bx = __float_as_uint(fxm);
    const unsigned by = __float_as_uint(fym);
    const unsigned off = bx * 16u + by * QROWB + (0u - MAGIC_BITS * (QROWB + 16u));

    const uint4 q  = __ldg((const uint4*)((const char*)qA + off));
    const uint4 q2 = __ldg((const uint4*)((const char*)qA + off + FAM_BYTES));

    const __half2 fx2 = __floats2half2_rn(fx, fx);

    {   const __half2 tb = __hfma2(fx2, *(const __half2*)&q.y, *(const __half2*)&q.x);
        const float2 f = __half22float2(tb);
        a0 += fmaf(fy, f.y - f.x, f.x); }
    {   const __half2 tb = __hfma2(fx2, *(const __half2*)&q.w, *(const __half2*)&q.z);
        const float2 f = __half22float2(tb);
        a1 += fmaf(fy, f.y - f.x, f.x); }
    {   const __half2 tb = __hfma2(fx2, *(const __half2*)&q2.y, *(const __half2*)&q2.x);
        const float2 f = __half22float2(tb);
        a2 += fmaf(fy, f.y - f.x, f.x); }
    {   const __half2 tb = __hfma2(fx2, *(const __half2*)&q2.w, *(const __half2*)&q2.z);
        const float2 f = __half22float2(tb);
        a3 += fmaf(fy, f.y - f.x, f.x); }
}

// Run [h0,h1) split into clamped-edge / clamp-free-interior / clamped-edge,
// stepping S with phase p. Exact partition given hs<=his<=hie<=he.
template<int S>
__device__ __forceinline__ void run_span(const uint4* __restrict__ qA,
                                         float X0, float dX, float Y0, float dY,
                                         int h0, int h1, int his, int hie, int p,
                                         float& a0, float& a1, float& a2, float& a3) {
    const int e1b = min(h1, his);
    const int itA = max(h0, his), itB = min(h1, hie);
    const int e2a = max(h0, hie);
    {   // edge 1 (clamped)
        int len = e1b - h0;
        if (len > 0) {
            int kmax = (len - p + S - 1) / S;
            float hf = (float)(h0 + p);
            for (int k = 0; k < kmax; ++k) {
                float X = fmaf(hf, dX, X0);
                float Y = fmaf(hf, dY, Y0);
                X = fminf(fmaxf(X, -1.0f), 512.0f);
                Y = fminf(fmaxf(Y, -1.0f), 512.0f);
                sample_accum4(qA, X, Y, a0, a1, a2, a3);
                hf += (float)S;
            }
        }
    }
    {   // interior (no clamps — identity there)
        int len = itB - itA;
        if (len > 0) {
            int kmax = (len - p + S - 1) / S;
            float hf = (float)(itA + p);
#pragma unroll 4
            for (int k = 0; k < kmax; ++k) {
                const float X = fmaf(hf, dX, X0);
                const float Y = fmaf(hf, dY, Y0);
                sample_accum4(qA, X, Y, a0, a1, a2, a3);
                hf += (float)S;
            }
        }
    }
    {   // edge 2 (clamped)
        int len = h1 - e2a;
        if (len > 0) {
            int kmax = (len - p + S - 1) / S;
            float hf = (float)(e2a + p);
            for (int k = 0; k < kmax; ++k) {
                float X = fmaf(hf, dX, X0);
                float Y = fmaf(hf, dY, Y0);
                X = fminf(fmaxf(X, -1.0f), 512.0f);
                Y = fminf(fmaxf(Y, -1.0f), 512.0f);
                sample_accum4(qA, X, Y, a0, a1, a2, a3);
                hf += (float)S;
            }
        }
    }
}

// Intervals from warp-uniform t-extremes [twA, twB]. Same math as R15.
__device__ __forceinline__ void make_intervals(float s, float c, float I0, float J0,
                                               float twA, float twB,
                                               int& hs, int& he, int& his, int& hie) {
    const float txA = fmaf(twA, c, I0), txB = fmaf(twB, c, I0);
    const float tyA = fmaf(twA, s, J0), tyB = fmaf(twB, s, J0);
    const float txmin = fminf(txA, txB), txmax = fmaxf(txA, txB);
    const float tymin = fminf(tyA, tyB), tymax = fmaxf(tyA, tyB);

    float hy0, hy1, hx0, hx1;
    if (fabsf(c) > 1e-5f) {
        const float inv = 1.0f / c;
        const float hA = (-1.0f - tymax) * inv;
        const float hB = (512.0f - tymin) * inv;
        hy0 = fminf(hA, hB); hy1 = fmaxf(hA, hB);
    } else { hy0 = 0.0f; hy1 = 511.0f; }
    if (s > 1e-5f) {
        const float inv = 1.0f / s;
        const float hA = (txmin - 512.0f) * inv;
        const float hB = (txmax + 1.0f) * inv;
        hx0 = fminf(hA, hB); hx1 = fmaxf(hA, hB);
    } else { hx0 = 0.0f; hx1 = 511.0f; }

    hs = __float2int_rd(fmaxf(fmaxf(hy0, hx0) - 1.0f, 0.0f));
    he = __float2int_ru(fminf(fminf(hy1, hx1) + 1.0f, 511.0f)) + 1;

    float xlo, xhi, ylo, yhi;
    if (s > 1e-2f) {
        const float inv = 1.0f / s;
        xlo = (txmax - 512.0f) * inv;
        xhi = (txmin + 1.0f) * inv;
    } else { xlo = -1e30f; xhi = 1e30f; }
    if (fabsf(c) > 1e-2f) {
        const float inv = 1.0f / c;
        const float hA = (-1.0f - tymin) * inv;
        const float hB = (512.0f - tymax) * inv;
        ylo = fminf(hA, hB); yhi = fmaxf(hA, hB);
    } else { ylo = -1e30f; yhi = 1e30f; }

    const float ilo = fmaxf(xlo, ylo) + 0.0625f;
    const float ihi = fminf(xhi, yhi) - 0.0625f;
    his = __float2int_ru(fminf(fmaxf(ilo, 0.0f), 520.0f));
    hie = __float2int_rd(fminf(fmaxf(ihi, -1.0f), 511.0f)) + 1;
    his = min(max(his, hs), he);
    hie = min(max(hie, his), he);
}

__global__ void __launch_bounds__(128, 10) radon_kernel(const float* __restrict__ angles,
                                                        float* __restrict__ out) {
    __shared__ float s_part[4][32];

    const int warp = threadIdx.x >> 5;
    const int lane = threadIdx.x & 31;
    const int tid  = threadIdx.x;

    const int t0blk = blockIdx.x * 32;
    const int n = blockIdx.y;        // angle pair theta = angles[n], theta+90

    const float ang = angles[n] * 0.017453292519943295f;
    const float s = sinf(ang);                     // theta in [0,90): s >= 0
    const float c = cosf(ang);
    const float ns = -s;

    const float I0 = 255.5f * (s - c + 1.0f);
    const float J0 = 255.5f * (1.0f - s - c);

    // transpose selection: row coord gets the smaller t-slope
    const bool tr = (s > fabsf(c));
    const uint4* __restrict__ qA = d_quads + (tr ? 2 : 0) * QELEMS;  // +QELEMS = img2 family

    // near-axis shape: rows(16t,2p)=16m+M < rows(8t,4p)=8m+3M  iff 4m < M
    const float m = fminf(s, fabsf(c));
    const float M = fmaxf(s, fabsf(c));
    const bool shapeB = (4.0f * m < M);

    if (!shapeB) {
        // ---- shape A: 8t x 4p, step 4 (bit-identical to R15 path) ----
        const int i = lane & 7;
        const int p = lane >> 3;
        const int tw0 = t0blk + warp * 8;
        const int t = tw0 + i;

        int hs, he, his, hie;
        make_intervals(s, c, I0, J0, (float)tw0, (float)(tw0 + 7), hs, he, his, hie);

        const float tix0 = fmaf((float)t, c, I0);
        const float tiy0 = fmaf((float)t, s, J0);
        const float X0 = tr ? tiy0 : tix0;
        const float dX = tr ? c    : ns;
        const float Y0 = tr ? tix0 : tiy0;
        const float dY = tr ? ns   : c;

        float a0 = 0.f, a1 = 0.f, a2 = 0.f, a3 = 0.f;
        run_span<4>(qA, X0, dX, Y0, dY, hs, he, his, hie, p, a0, a1, a2, a3);

        a0 += __shfl_xor_sync(0xffffffffu, a0, 8);
        a0 += __shfl_xor_sync(0xffffffffu, a0, 16);
        a1 += __shfl_xor_sync(0xffffffffu, a1, 8);
        a1 += __shfl_xor_sync(0xffffffffu, a1, 16);
        a2 += __shfl_xor_sync(0xffffffffu, a2, 8);
        a2 += __shfl_xor_sync(0xffffffffu, a2, 16);
        a3 += __shfl_xor_sync(0xffffffffu, a3, 8);
        a3 += __shfl_xor_sync(0xffffffffu, a3, 16);

        if (p == 0) {
            out[n * IMG + t] = a0;
            out[(NANG + n) * IMG + t] = a1;
            out[(n + 90) * IMG + t] = a2;
            out[(NANG + n + 90) * IMG + t] = a3;
        }
    } else {
        // ---- shape B: 16t x 2p, step 2; warp pairs split the h-range ----
        if (tid < 128) {
            ((float*)s_part)[tid] = 0.0f;
        }
        __syncthreads();

        const int i = lane & 15;
        const int p = lane >> 4;          // 0 or 1
        const int wB = warp & 1;          // t-half
        const int hH = warp >> 1;         // h-half
        const int tw0 = t0blk + wB * 16;
        const int t = tw0 + i;

        int hs, he, his, hie;
        make_intervals(s, c, I0, J0, (float)tw0, (float)(tw0 + 15), hs, he, his, hie);
        const int hmid = (hs + he) >> 1;
        const int h0 = hH ? hmid : hs;
        const int h1 = hH ? he : hmid;

        const float tix0 = fmaf((float)t, c, I0);
        const float tiy0 = fmaf((float)t, s, J0);
        const float X0 = tr ? tiy0 : tix0;
        const float dX = tr ? c    : ns;
        const float Y0 = tr ? tix0 : tiy0;
        const float dY = tr ? ns   : c;

        float a0 = 0.f, a1 = 0.f, a2 = 0.f, a3 = 0.f;
        run_span<2>(qA, X0, dX, Y0, dY, h0, h1, his, hie, p, a0, a1, a2, a3);

        a0 += __shfl_xor_sync(0xffffffffu, a0, 16);
        a1 += __shfl_xor_sync(0xffffffffu, a1, 16);
        a2 += __shfl_xor_sync(0xffffffffu, a2, 16);
        a3 += __shfl_xor_sync(0xffffffffu, a3, 16);

        if (p == 0) {
            const int t32 = wB * 16 + i;
            atomicAdd(&s_part[0][t32], a0);
            atomicAdd(&s_part[1][t32], a1);
            atomicAdd(&s_part[2][t32], a2);
            atomicAdd(&s_part[3][t32], a3);
        }
        __syncthreads();

        if (tid < 128) {
            const int a  = tid >> 5;
            const int tt = t0blk + (tid & 31);
            const float v = s_part[a][tid & 31];
            if (a == 0)      out[n * IMG + tt] = v;
            else if (a == 1) out[(NANG + n) * IMG + tt] = v;
            else if (a == 2) out[(n + 90) * IMG + tt] = v;
            else             out[(NANG + n + 90) * IMG + tt] = v;
        }
    }
}

extern "C" void kernel_launch(void* const* d_in, const int* in_sizes, int n_in,
                              void* d_out, int out_size) {
    const float* x      = (const float*)d_in[0];   // [2,1,512,512]
    const float* angles = (const float*)d_in[1];   // [180]
    float* out          = (float*)d_out;           // [2,180,512]

    {
        int threads = 256;
        int blocks = (QELEMS + threads - 1) / threads;
        quad_kernel<<<blocks, threads>>>(x);
    }
    {
        dim3 block(128, 1, 1);
        dim3 grid(IMG / 32, 90, 1);   // 16 x 90 = 1440 blocks
        radon_kernel<<<grid, block>>>(angles, out);
    }
}

// round 17
// speedup vs baseline: 1.0237x; 1.0237x over previous
#include <cuda_runtime.h>
#include <cuda_fp16.h>
#include <cstdint>

// Radon transform: out[b, n, t] = sum_h bilinear(img_b, R(theta_n) * grid(t, h))
// B=2, N=180 (angles = 0..179 deg), H=W=512.
//
// BATCH + ANGLE fusion: each warp-iteration -> 4 outputs (2 batches x {theta,
// theta+90}) from 2 LDG.128 of batch-packed fp16 delta-quads (img and
// img2(r,c)=img(c,511-r)); transposed families keep the L1 row-slope at
// min(|s|,|c|). Magic floor/fract, clamp-free interior, h-interval zero skip.
// Prologue stages a 33x33 pixel apron in smem per 32x32-cell tile and emits all
// 4 quad families with COALESCED stores. 64-thread blocks for load balance.

#define IMG 512
#define NANG 180
#define QPITCH 516                    // quad row pitch; valid rows/cols 0..515
#define QELEMS (QPITCH * QPITCH)
#define MAGIC1 12582913.0f            // 2^23 + 2^22 + 1
#define MAGIC_BITS 0x4B400000u        // float bits of 12582912.0f
#define QROWB (QPITCH * 16u)          // bytes per quad row
#define FAM_BYTES (QELEMS * 16u)      // family stride in bytes

// families: 0 = img normal, 1 = img2 normal, 2 = img transposed, 3 = img2 transposed
__device__ uint4 d_quads[4 * QELEMS];

__device__ __forceinline__ float pix(const float* img, int r, int c) {
    return ((unsigned)r < IMG && (unsigned)c < IMG) ? img[r * IMG + c] : 0.0f;
}
__device__ __forceinline__ unsigned packh2(float a, float b) {
    __half2 h = __floats2half2_rn(a, b);
    return *(const unsigned int*)&h;
}

#define APR 33   // apron extent (33x33 pixels per tile per batch)

__global__ void __launch_bounds__(256) quad_kernel(const float* __restrict__ x) {
    __shared__ float sA[APR * APR];
    __shared__ float sB[APR * APR];

    const int tid = threadIdx.x;
    const int r0 = blockIdx.y * 32;
    const int c0 = blockIdx.x * 32;

    const float* img0 = x;
    const float* img1 = x + IMG * IMG;

    for (int k = tid; k < APR * APR; k += 256) {
        int ar = k / APR, ac = k - ar * APR;
        int gr = r0 - 1 + ar, gc = c0 - 1 + ac;
        sA[k] = pix(img0, gr, gc);
        sB[k] = pix(img1, gr, gc);
    }
    __syncthreads();

    // Phase 1 — cc fastest: N (row-major) and T2 (row gr, col 512-gc) coalesced.
    for (int k = 0; k < 4; ++k) {
        const int lin = k * 256 + tid;
        const int r  = lin >> 5;
        const int cc = lin & 31;
        const int gr = r0 + r, gc = c0 + cc;
        if (gr >= QPITCH) continue;
        const float a00 = sA[r * APR + cc],       a10 = sA[r * APR + cc + 1];
        const float a01 = sA[(r + 1) * APR + cc], a11 = sA[(r + 1) * APR + cc + 1];
        const float b00 = sB[r * APR + cc],       b10 = sB[r * APR + cc + 1];
        const float b01 = sB[(r + 1) * APR + cc], b11 = sB[(r + 1) * APR + cc + 1];
        if (gc < QPITCH) {         // img normal at (gr, gc)
            uint4 q;
            q.x = packh2(a00, a01); q.y = packh2(a10 - a00, a11 - a01);
            q.z = packh2(b00, b01); q.w = packh2(b10 - b00, b11 - b01);
            d_quads[0 * QELEMS + gr * QPITCH + gc] = q;
        }
        if (gc <= 512) {           // img2 transposed at (gr, 512-gc)
            uint4 q;
            q.x = packh2(a10, a11); q.y = packh2(a00 - a10, a01 - a11);
            q.z = packh2(b10, b11); q.w = packh2(b00 - b10, b01 - b11);
            d_quads[3 * QELEMS + gr * QPITCH + (512 - gc)] = q;
        }
    }

    // Phase 2 — r fastest: T (row gc, col gr) and N2 (row 512-gc, col gr) coalesced.
    for (int k = 0; k < 4; ++k) {
        const int lin = k * 256 + tid;
        const int cc = lin >> 5;
        const int r  = lin & 31;
        const int gr = r0 + r, gc = c0 + cc;
        if (gr >= QPITCH) continue;
        const float a00 = sA[r * APR + cc],       a10 = sA[r * APR + cc + 1];
        const float a01 = sA[(r + 1) * APR + cc], a11 = sA[(r + 1) * APR + cc + 1];
        const float b00 = sB[r * APR + cc],       b10 = sB[r * APR + cc + 1];
        const float b01 = sB[(r + 1) * APR + cc], b11 = sB[(r + 1) * APR + cc + 1];
        if (gc < QPITCH) {         // img transposed at (gc, gr)
            uint4 q;
            q.x = packh2(a00, a10); q.y = packh2(a01 - a00, a11 - a10);
            q.z = packh2(b00, b10); q.w = packh2(b01 - b00, b11 - b10);
            d_quads[2 * QELEMS + gc * QPITCH + gr] = q;
        }
        if (gc <= 512) {           // img2 normal at (512-gc, gr)
            uint4 q;
            q.x = packh2(a10, a00); q.y = packh2(a11 - a10, a01 - a00);
            q.z = packh2(b10, b00); q.w = packh2(b11 - b10, b01 - b00);
            d_quads[1 * QELEMS + (512 - gc) * QPITCH + gr] = q;
        }
    }

    // img2 rows/cols 513..515 (never produced by the map above) are all-zero.
    if (blockIdx.x == 0 && blockIdx.y == 0) {
        const uint4 z = make_uint4(0u, 0u, 0u, 0u);
        for (int e = 513; e < QPITCH; ++e) {
            for (int j = tid; j < QPITCH; j += 256) {
                d_quads[1 * QELEMS + e * QPITCH + j] = z;
                d_quads[3 * QELEMS + j * QPITCH + e] = z;
            }
        }
    }
}

// X = fast coord, Y = row coord; both in [-1, 512]. One call -> 4 outputs.
__device__ __forceinline__ void sample_accum4(const uint4* __restrict__ qA,
                                              float X, float Y,
                                              float& a0, float& a1,
                                              float& a2, float& a3) {
    const float fxm = __fadd_rd(X, MAGIC1);
    const float fym = __fadd_rd(Y, MAGIC1);
    const float fx = X - (fxm - MAGIC1);
    const float fy = Y - (fym - MAGIC1);

    const unsigned bx = __float_as_uint(fxm);
    const unsigned by = __float_as_uint(fym);
    const unsigned off = bx * 16u + by * QROWB + (0u - MAGIC_BITS * (QROWB + 16u));

    const uint4 q  = __ldg((const uint4*)((const char*)qA + off));
    const uint4 q2 = __ldg((const uint4*)((const char*)qA + off + FAM_BYTES));

    const __half2 fx2 = __floats2half2_rn(fx, fx);

    {   const __half2 tb = __hfma2(fx2, *(const __half2*)&q.y, *(const __half2*)&q.x);
        const float2 f = __half22float2(tb);
        a0 += fmaf(fy, f.y - f.x, f.x); }
    {   const __half2 tb = __hfma2(fx2, *(const __half2*)&q.w, *(const __half2*)&q.z);
        const float2 f = __half22float2(tb);
        a1 += fmaf(fy, f.y - f.x, f.x); }
    {   const __half2 tb = __hfma2(fx2, *(const __half2*)&q2.y, *(const __half2*)&q2.x);
        const float2 f = __half22float2(tb);
        a2 += fmaf(fy, f.y - f.x, f.x); }
    {   const __half2 tb = __hfma2(fx2, *(const __half2*)&q2.w, *(const __half2*)&q2.z);
        const float2 f = __half22float2(tb);
        a3 += fmaf(fy, f.y - f.x, f.x); }
}

__global__ void __launch_bounds__(64) radon_kernel(const float* __restrict__ angles,
                                                   float* __restrict__ out) {
    const int warp = threadIdx.x >> 5;     // 0..1
    const int lane = threadIdx.x & 31;
    const int i = lane & 7;                // t within warp's 8-wide tile
    const int p = lane >> 3;               // h phase 0..3

    const int t0 = blockIdx.x * 16 + warp * 8;
    const int t = t0 + i;
    const int n = blockIdx.y;              // theta = angles[n], theta+90 = angles[n+90]

    const float ang = angles[n] * 0.017453292519943295f;
    const float s = sinf(ang);             // theta in [0,90): s >= 0
    const float c = cosf(ang);
    const float ns = -s;

    const float I0 = 255.5f * (s - c + 1.0f);
    const float J0 = 255.5f * (1.0f - s - c);

    const float tix0 = fmaf((float)t, c, I0);
    const float tiy0 = fmaf((float)t, s, J0);

    const float txA = fmaf((float)t0, c, I0), txB = fmaf((float)(t0 + 7), c, I0);
    const float tyA = fmaf((float)t0, s, J0), tyB = fmaf((float)(t0 + 7), s, J0);
    const float txmin = fminf(txA, txB), txmax = fmaxf(txA, txB);
    const float tymin = fminf(tyA, tyB), tymax = fmaxf(tyA, tyB);

    // ---- outer interval: SOME lane nonzero (ix,iy in (-1,512)), padded +-1 ----
    float hy0, hy1, hx0, hx1;
    if (fabsf(c) > 1e-5f) {
        const float inv = 1.0f / c;
        const float hA = (-1.0f - tymax) * inv;
        const float hB = (512.0f - tymin) * inv;
        hy0 = fminf(hA, hB); hy1 = fmaxf(hA, hB);
    } else { hy0 = 0.0f; hy1 = 511.0f; }
    if (s > 1e-5f) {
        const float inv = 1.0f / s;
        const float hA = (txmin - 512.0f) * inv;
        const float hB = (txmax + 1.0f) * inv;
        hx0 = fminf(hA, hB); hx1 = fmaxf(hA, hB);
    } else { hx0 = 0.0f; hx1 = 511.0f; }

    const int hs = __float2int_rd(fmaxf(fmaxf(hy0, hx0) - 1.0f, 0.0f));
    const int he = __float2int_ru(fminf(fminf(hy1, hx1) + 1.0f, 511.0f)) + 1;

    // ---- interior interval: ALL lanes in [-1,512] (clamps identity) ----
    float xlo, xhi, ylo, yhi;
    if (s > 1e-2f) {
        const float inv = 1.0f / s;
        xlo = (txmax - 512.0f) * inv;
        xhi = (txmin + 1.0f) * inv;
    } else { xlo = -1e30f; xhi = 1e30f; }
    if (fabsf(c) > 1e-2f) {
        const float inv = 1.0f / c;
        const float hA = (-1.0f - tymin) * inv;
        const float hB = (512.0f - tymax) * inv;
        ylo = fminf(hA, hB); yhi = fmaxf(hA, hB);
    } else { ylo = -1e30f; yhi = 1e30f; }

    const float ilo = fmaxf(xlo, ylo) + 0.0625f;
    const float ihi = fminf(xhi, yhi) - 0.0625f;
    int his = __float2int_ru(fminf(fmaxf(ilo, 0.0f), 520.0f));
    int hie = __float2int_rd(fminf(fmaxf(ihi, -1.0f), 511.0f)) + 1;
    his = min(max(his, hs), he);
    hie = min(max(hie, his), he);

    // ---- transpose selection: row coord gets the smaller t-slope ----
    const bool tr = (s > fabsf(c));
    const uint4* __restrict__ qA = d_quads + (tr ? 2 : 0) * QELEMS;  // +FAM = img2
    const float X0 = tr ? tiy0 : tix0;
    const float dX = tr ? c    : ns;
    const float Y0 = tr ? tix0 : tiy0;
    const float dY = tr ? ns   : c;

    float a0 = 0.f, a1 = 0.f, a2 = 0.f, a3 = 0.f;

    // edge 1: [hs, his) with clamps
    {
        const int kmax = (his - hs - p + 3) >> 2;
        float hf = (float)(hs + p);
        for (int k = 0; k < kmax; ++k) {
            float X = fmaf(hf, dX, X0);
            float Y = fmaf(hf, dY, Y0);
            X = fminf(fmaxf(X, -1.0f), 512.0f);
            Y = fminf(fmaxf(Y, -1.0f), 512.0f);
            sample_accum4(qA, X, Y, a0, a1, a2, a3);
            hf += 4.0f;
        }
    }
    // interior: [his, hie) no clamps
    {
        const int kmax = (hie - his - p + 3) >> 2;
        float hf = (float)(his + p);
#pragma unroll 4
        for (int k = 0; k < kmax; ++k) {
            const float X = fmaf(hf, dX, X0);
            const float Y = fmaf(hf, dY, Y0);
            sample_accum4(qA, X, Y, a0, a1, a2, a3);
            hf += 4.0f;
        }
    }
    // edge 2: [hie, he) with clamps
    {
        const int kmax = (he - hie - p + 3) >> 2;
        float hf = (float)(hie + p);
        for (int k = 0; k < kmax; ++k) {
            float X = fmaf(hf, dX, X0);
            float Y = fmaf(hf, dY, Y0);
            X = fminf(fmaxf(X, -1.0f), 512.0f);
            Y = fminf(fmaxf(Y, -1.0f), 512.0f);
            sample_accum4(qA, X, Y, a0, a1, a2, a3);
            hf += 4.0f;
        }
    }

    // Fold the 4 h-phases.
    a0 += __shfl_xor_sync(0xffffffffu, a0, 8);
    a0 += __shfl_xor_sync(0xffffffffu, a0, 16);
    a1 += __shfl_xor_sync(0xffffffffu, a1, 8);
    a1 += __shfl_xor_sync(0xffffffffu, a1, 16);
    a2 += __shfl_xor_sync(0xffffffffu, a2, 8);
    a2 += __shfl_xor_sync(0xffffffffu, a2, 16);
    a3 += __shfl_xor_sync(0xffffffffu, a3, 8);
    a3 += __shfl_xor_sync(0xffffffffu, a3, 16);

    if (p == 0) {
        out[n * IMG + t] = a0;                        // b0, theta
        out[(NANG + n) * IMG + t] = a1;               // b1, theta
        out[(n + 90) * IMG + t] = a2;                 // b0, theta+90
        out[(NANG + n + 90) * IMG + t] = a3;          // b1, theta+90
    }
}

extern "C" void kernel_launch(void* const* d_in, const int* in_sizes, int n_in,
                              void* d_out, int out_size) {
    const float* x      = (const float*)d_in[0];   // [2,1,512,512]
    const float* angles = (const float*)d_in[1];   // [180]
    float* out          = (float*)d_out;           // [2,180,512]

    {
        dim3 block(256, 1, 1);
        dim3 grid(17, 17, 1);            // 32x32-cell tiles covering 516x516
        quad_kernel<<<grid, block>>>(x);
    }
    {
        dim3 block(64, 1, 1);
        dim3 grid(IMG / 16, 90, 1);      // 32 x 90 = 2880 blocks, 2 warps each
        radon_kernel<<<grid, block>>>(angles, out);
    }
}